// round 10
// baseline (speedup 1.0000x reference)
#include <cuda_runtime.h>
#include <cstdint>

// Fixed shapes: x [4,512,128] -> Q=2048 rows, y [512,128] -> M=512, D=128,
// out [Q, M, 3] f32 (cos, p1, p2).
#define Q_TOT 2048
#define M_TOT 512
#define D_TOT 128

typedef unsigned long long ull;

// ---------------- packed f32x2 helpers ----------------
__device__ __forceinline__ ull f32x2_add(ull a, ull b) {
    ull r; asm("add.rn.f32x2 %0, %1, %2;" : "=l"(r) : "l"(a), "l"(b)); return r;
}
__device__ __forceinline__ ull f32x2_fma(ull a, ull b, ull c) {
    ull r; asm("fma.rn.f32x2 %0, %1, %2, %3;" : "=l"(r) : "l"(a), "l"(b), "l"(c)); return r;
}
__device__ __forceinline__ ull pack2(float a, float b) {
    ull r; asm("mov.b64 %0, {%1, %2};" : "=l"(r) : "f"(a), "f"(b)); return r;
}
__device__ __forceinline__ float lo32(ull v) { return __uint_as_float((unsigned)v); }
__device__ __forceinline__ float hi32(ull v) { return __uint_as_float((unsigned)(v >> 32)); }
__device__ __forceinline__ float sqrt_ap(float x) {
    float r; asm("sqrt.approx.f32 %0, %1;" : "=f"(r) : "f"(x)); return r;
}
__device__ __forceinline__ float rsqrt_ap(float x) {
    float r; asm("rsqrt.approx.f32 %0, %1;" : "=f"(r) : "f"(x)); return r;
}

// ---------------- fused distance kernel ----------------
// Tile: 32 q x 32 m per CTA, 64 threads (tx=tid&7 -> m, ty=tid>>3 -> q), 4x4 per thread.
// D processed as 64 f32x2-pairs in 2 chunks of 32 dpairs (64 floats), staged in SMEM
// as [dpair][row]. y is staged NEGATED so diff = add.f32x2(x2, ny2).
// Row norms (for cos via polarization) computed in-kernel from the staged tiles:
// thread t owns staged row t (t<32: x-row, t>=32: y-row).
__global__ __launch_bounds__(64, 10) void dist_main(
    const float* __restrict__ x, const float* __restrict__ y, float* __restrict__ out)
{
    __shared__ __align__(16) ull sx[32][33];   // [dpair][q_local], +1 ull pad
    __shared__ __align__(16) ull sy[32][33];   // [dpair][m_local], holds -y
    __shared__ float s_xn2[32], s_xrn[32], s_yn2[32], s_yrn[32];

    const int tid = threadIdx.x;
    const int tx = tid & 7;          // m direction
    const int ty = tid >> 3;         // q direction
    const int q0 = blockIdx.y * 32;
    const int m0 = blockIdx.x * 32;

    ull accL[4][4];  // packed L1 partial sums
    ull accS[4][4];  // packed squared-diff partial sums
    #pragma unroll
    for (int i = 0; i < 4; i++)
        #pragma unroll
        for (int j = 0; j < 4; j++) { accL[i][j] = 0ull; accS[i][j] = 0ull; }

    float na = 0.0f, nb = 0.0f;      // this thread's row-norm partials

    const float4* x4 = reinterpret_cast<const float4*>(x);
    const float4* y4 = reinterpret_cast<const float4*>(y);

    for (int c = 0; c < 2; ++c) {
        // ---- stage chunk c: 64 rows (32 x + 32 y) x 64 floats = 16 float4 each ----
        // 1024 float4 loads over 64 threads -> 16 iterations. row advances 4 per t,
        // so the x/y branch flips exactly at t=8 and stays warp-uniform throughout.
        #pragma unroll
        for (int t = 0; t < 16; ++t) {
            int idx = tid + t * 64;       // 0..1023
            int row = idx >> 4;           // 0..63
            int c4  = idx & 15;           // float4 column within chunk (0..15)
            if (row < 32) {
                float4 v = x4[(size_t)(q0 + row) * (D_TOT / 4) + c * 16 + c4];
                sx[c4 * 2][row]     = pack2(v.x, v.y);
                sx[c4 * 2 + 1][row] = pack2(v.z, v.w);
            } else {
                int r = row - 32;
                float4 v = y4[(size_t)(m0 + r) * (D_TOT / 4) + c * 16 + c4];
                sy[c4 * 2][r]     = pack2(-v.x, -v.y);
                sy[c4 * 2 + 1][r] = pack2(-v.z, -v.w);
            }
        }
        __syncthreads();

        // ---- norm partial: thread t owns staged row t (conflict-free LDS) ----
        {
            const ull* src = (tid < 32) ? &sx[0][tid] : &sy[0][tid - 32];
            #pragma unroll 8
            for (int dp = 0; dp < 32; dp += 2) {
                ull v0 = src[(size_t)dp * 33];
                ull v1 = src[(size_t)(dp + 1) * 33];
                float a0 = lo32(v0), b0 = hi32(v0);
                float a1 = lo32(v1), b1 = hi32(v1);
                na = fmaf(a0, a0, fmaf(b0, b0, na));
                nb = fmaf(a1, a1, fmaf(b1, b1, nb));
            }
        }

        // ---- compute: 32 dpairs, 16 packed pairs per thread per dpair ----
        #pragma unroll 4
        for (int dp = 0; dp < 32; ++dp) {
            ull xr[4], yr[4];
            #pragma unroll
            for (int i = 0; i < 4; i++) xr[i] = sx[dp][ty * 4 + i];
            #pragma unroll
            for (int j = 0; j < 4; j++) yr[j] = sy[dp][tx * 4 + j];
            #pragma unroll
            for (int i = 0; i < 4; i++) {
                #pragma unroll
                for (int j = 0; j < 4; j++) {
                    ull d  = f32x2_add(xr[i], yr[j]);            // x - y (packed)
                    ull ad = d & 0x7FFFFFFF7FFFFFFFull;          // packed |.| (2x LOP3, alu pipe)
                    accL[i][j] = f32x2_add(accL[i][j], ad);
                    accS[i][j] = f32x2_fma(d, d, accS[i][j]);
                }
            }
        }
        __syncthreads();   // before restage (chunk 0) / before norm publish (chunk 1)
    }

    // ---- publish norms (norm of -y == norm of y) ----
    {
        float n2 = na + nb;
        float rn = rsqrt_ap(n2);
        if (tid < 32) { s_xn2[tid] = n2; s_xrn[tid] = rn; }
        else          { s_yn2[tid - 32] = n2; s_yrn[tid - 32] = rn; }
    }
    __syncthreads();

    // ---- epilogue: fold packed halves, cos via polarization identity ----
    float xn2[4], xrn[4], yn2[4], yrn[4];
    #pragma unroll
    for (int i = 0; i < 4; i++) { xn2[i] = s_xn2[ty * 4 + i]; xrn[i] = s_xrn[ty * 4 + i]; }
    #pragma unroll
    for (int j = 0; j < 4; j++) { yn2[j] = s_yn2[tx * 4 + j]; yrn[j] = s_yrn[tx * 4 + j]; }

    #pragma unroll
    for (int i = 0; i < 4; i++) {
        int q = q0 + ty * 4 + i;
        float r[12];
        #pragma unroll
        for (int j = 0; j < 4; j++) {
            float l1 = lo32(accL[i][j]) + hi32(accL[i][j]);
            float sq = lo32(accS[i][j]) + hi32(accS[i][j]);
            float p2 = sqrt_ap(sq);
            // x.y = (||x||^2 + ||y||^2 - ||x-y||^2) / 2 ; cos = x.y / (||x|| ||y||)
            float cs = (xn2[i] + yn2[j] - sq) * 0.5f * xrn[i] * yrn[j];
            r[3 * j + 0] = cs;
            r[3 * j + 1] = l1;
            r[3 * j + 2] = p2;
        }
        // 4 consecutive m -> 12 contiguous floats, 48B-aligned: 3x STG.128
        float4* o = reinterpret_cast<float4*>(out + ((size_t)q * M_TOT + (m0 + tx * 4)) * 3);
        o[0] = make_float4(r[0], r[1], r[2],  r[3]);
        o[1] = make_float4(r[4], r[5], r[6],  r[7]);
        o[2] = make_float4(r[8], r[9], r[10], r[11]);
    }
}

extern "C" void kernel_launch(void* const* d_in, const int* in_sizes, int n_in,
                              void* d_out, int out_size) {
    const float* x = (const float*)d_in[0];   // [4,512,128]
    const float* y = (const float*)d_in[1];   // [512,128]
    float* out = (float*)d_out;               // [4,512,512,3]

    dim3 grid(M_TOT / 32, Q_TOT / 32);        // (16, 64) = 1024 CTAs
    dist_main<<<grid, 64>>>(x, y, out);
}

// round 11
// speedup vs baseline: 1.0748x; 1.0748x over previous
#include <cuda_runtime.h>
#include <cstdint>

// Fixed shapes: x [4,512,128] -> Q=2048 rows, y [512,128] -> M=512, D=128,
// out [Q, M, 3] f32 (cos, p1, p2).
#define Q_TOT 2048
#define M_TOT 512
#define D_TOT 128

typedef unsigned long long ull;

// ---------------- packed f32x2 helpers ----------------
__device__ __forceinline__ ull f32x2_add(ull a, ull b) {
    ull r; asm("add.rn.f32x2 %0, %1, %2;" : "=l"(r) : "l"(a), "l"(b)); return r;
}
__device__ __forceinline__ ull f32x2_fma(ull a, ull b, ull c) {
    ull r; asm("fma.rn.f32x2 %0, %1, %2, %3;" : "=l"(r) : "l"(a), "l"(b), "l"(c)); return r;
}
__device__ __forceinline__ ull pack2(float a, float b) {
    ull r; asm("mov.b64 %0, {%1, %2};" : "=l"(r) : "f"(a), "f"(b)); return r;
}
__device__ __forceinline__ float lo32(ull v) { return __uint_as_float((unsigned)v); }
__device__ __forceinline__ float hi32(ull v) { return __uint_as_float((unsigned)(v >> 32)); }
__device__ __forceinline__ float sqrt_ap(float x) {
    float r; asm("sqrt.approx.f32 %0, %1;" : "=f"(r) : "f"(x)); return r;
}
__device__ __forceinline__ float rsqrt_ap(float x) {
    float r; asm("rsqrt.approx.f32 %0, %1;" : "=f"(r) : "f"(x)); return r;
}

// ---------------- fused distance kernel ----------------
// Tile: 32 q x 32 m per CTA, 128 threads (tx=tid&15 -> m pairs, ty=tid>>4 -> q quads),
// 4q x 2m outputs per thread. D processed as 64 f32x2-pairs in 2 chunks of 32 dpairs,
// staged in SMEM as [dpair][row] with rows padded to 34 ull (272B, 16B-multiple) so
// the compute loop can use 128-bit LDS. y is staged NEGATED: diff = add.f32x2(x, -y).
// Row norms (for cos via polarization) computed in-kernel from staged tiles:
// threads (tid&63) own rows, split dp-range by (tid>>6).
__global__ __launch_bounds__(128, 6) void dist_main(
    const float* __restrict__ x, const float* __restrict__ y, float* __restrict__ out)
{
    __shared__ __align__(16) ull sx[32][34];   // [dpair][q_local]
    __shared__ __align__(16) ull sy[32][34];   // [dpair][m_local], holds -y
    __shared__ float s_part[128];
    __shared__ float s_xn2[32], s_xrn[32], s_yn2[32], s_yrn[32];

    const int tid = threadIdx.x;
    const int tx = tid & 15;         // m direction (2 cols each)
    const int ty = tid >> 4;         // q direction (4 rows each)
    const int q0 = blockIdx.y * 32;
    const int m0 = blockIdx.x * 32;

    ull accL[4][2];  // packed L1 partial sums
    ull accS[4][2];  // packed squared-diff partial sums
    #pragma unroll
    for (int i = 0; i < 4; i++)
        #pragma unroll
        for (int j = 0; j < 2; j++) { accL[i][j] = 0ull; accS[i][j] = 0ull; }

    float na = 0.0f, nb = 0.0f;      // row-norm partials (this thread's half-row)
    const int nrow  = tid & 63;      // staged row owned for norm (0..31 x, 32..63 y)
    const int nhalf = tid >> 6;      // which 16 dpairs of that row

    const float4* x4 = reinterpret_cast<const float4*>(x);
    const float4* y4 = reinterpret_cast<const float4*>(y);

    for (int c = 0; c < 2; ++c) {
        // ---- stage chunk c: 64 rows (32 x + 32 y) x 64 floats = 16 float4 each ----
        // 1024 float4 over 128 threads -> 8 iters; rows advance 8/iter so the x/y
        // branch flips exactly at t=4 and stays warp-uniform.
        #pragma unroll
        for (int t = 0; t < 8; ++t) {
            int idx = tid + t * 128;      // 0..1023
            int row = idx >> 4;           // 0..63
            int c4  = idx & 15;           // float4 column within chunk
            if (row < 32) {
                float4 v = x4[(size_t)(q0 + row) * (D_TOT / 4) + c * 16 + c4];
                sx[c4 * 2][row]     = pack2(v.x, v.y);
                sx[c4 * 2 + 1][row] = pack2(v.z, v.w);
            } else {
                int r = row - 32;
                float4 v = y4[(size_t)(m0 + r) * (D_TOT / 4) + c * 16 + c4];
                sy[c4 * 2][r]     = pack2(-v.x, -v.y);
                sy[c4 * 2 + 1][r] = pack2(-v.z, -v.w);
            }
        }
        __syncthreads();

        // ---- norm partial: 2 threads per staged row, 16 dpairs each ----
        {
            const ull* src = (nrow < 32) ? &sx[0][nrow] : &sy[0][nrow - 32];
            src += (size_t)(nhalf * 16) * 34;
            #pragma unroll 8
            for (int dp = 0; dp < 16; dp += 2) {
                ull v0 = src[(size_t)dp * 34];
                ull v1 = src[(size_t)(dp + 1) * 34];
                float a0 = lo32(v0), b0 = hi32(v0);
                float a1 = lo32(v1), b1 = hi32(v1);
                na = fmaf(a0, a0, fmaf(b0, b0, na));
                nb = fmaf(a1, a1, fmaf(b1, b1, nb));
            }
        }

        // ---- compute: 32 dpairs, 8 packed pairs per thread per dpair ----
        #pragma unroll 4
        for (int dp = 0; dp < 32; ++dp) {
            // xr: 2x LDS.128 (2 distinct addrs per warp -> broadcast)
            ulonglong2 xa = *reinterpret_cast<const ulonglong2*>(&sx[dp][ty * 4]);
            ulonglong2 xb = *reinterpret_cast<const ulonglong2*>(&sx[dp][ty * 4 + 2]);
            // yr: 1x LDS.128 (16 distinct 16B addrs -> 2-phase)
            ulonglong2 yv = *reinterpret_cast<const ulonglong2*>(&sy[dp][tx * 2]);
            ull xr[4] = { xa.x, xa.y, xb.x, xb.y };
            ull yr[2] = { yv.x, yv.y };
            #pragma unroll
            for (int i = 0; i < 4; i++) {
                #pragma unroll
                for (int j = 0; j < 2; j++) {
                    ull d  = f32x2_add(xr[i], yr[j]);            // x - y (packed)
                    ull ad = d & 0x7FFFFFFF7FFFFFFFull;          // packed |.| (alu pipe)
                    accL[i][j] = f32x2_add(accL[i][j], ad);
                    accS[i][j] = f32x2_fma(d, d, accS[i][j]);
                }
            }
        }
        __syncthreads();   // before restage (chunk 0) / before norm publish (chunk 1)
    }

    // ---- publish norms: combine the two half-row partials ----
    s_part[tid] = na + nb;
    __syncthreads();
    if (tid < 64) {
        float n2 = s_part[tid] + s_part[tid + 64];
        float rn = rsqrt_ap(n2);
        if (tid < 32) { s_xn2[tid] = n2; s_xrn[tid] = rn; }
        else          { s_yn2[tid - 32] = n2; s_yrn[tid - 32] = rn; }
    }
    __syncthreads();

    // ---- epilogue: fold packed halves, cos via polarization identity ----
    float xn2[4], xrn[4], yn2[2], yrn[2];
    #pragma unroll
    for (int i = 0; i < 4; i++) { xn2[i] = s_xn2[ty * 4 + i]; xrn[i] = s_xrn[ty * 4 + i]; }
    #pragma unroll
    for (int j = 0; j < 2; j++) { yn2[j] = s_yn2[tx * 2 + j]; yrn[j] = s_yrn[tx * 2 + j]; }

    #pragma unroll
    for (int i = 0; i < 4; i++) {
        int q = q0 + ty * 4 + i;
        float r[6];
        #pragma unroll
        for (int j = 0; j < 2; j++) {
            float l1 = lo32(accL[i][j]) + hi32(accL[i][j]);
            float sq = lo32(accS[i][j]) + hi32(accS[i][j]);
            float p2 = sqrt_ap(sq);
            // x.y = (||x||^2 + ||y||^2 - ||x-y||^2) / 2 ; cos = x.y / (||x|| ||y||)
            float cs = (xn2[i] + yn2[j] - sq) * 0.5f * xrn[i] * yrn[j];
            r[3 * j + 0] = cs;
            r[3 * j + 1] = l1;
            r[3 * j + 2] = p2;
        }
        // 2 consecutive m -> 6 contiguous floats at 24B-multiple offset (8B aligned):
        // 3x STG.64
        float2* o = reinterpret_cast<float2*>(out + ((size_t)q * M_TOT + (m0 + tx * 2)) * 3);
        o[0] = make_float2(r[0], r[1]);
        o[1] = make_float2(r[2], r[3]);
        o[2] = make_float2(r[4], r[5]);
    }
}

extern "C" void kernel_launch(void* const* d_in, const int* in_sizes, int n_in,
                              void* d_out, int out_size) {
    const float* x = (const float*)d_in[0];   // [4,512,128]
    const float* y = (const float*)d_in[1];   // [512,128]
    float* out = (float*)d_out;               // [4,512,512,3]

    dim3 grid(M_TOT / 32, Q_TOT / 32);        // (16, 64) = 1024 CTAs, 4096 warps
    dist_main<<<grid, 128>>>(x, y, out);
}

// round 16
// speedup vs baseline: 1.0760x; 1.0012x over previous
#include <cuda_runtime.h>
#include <cstdint>

// Fixed shapes: x [4,512,128] -> Q=2048 rows, y [512,128] -> M=512, D=128,
// out [Q, M, 3] f32 (cos, p1, p2).
#define Q_TOT 2048
#define M_TOT 512
#define D_TOT 128

typedef unsigned long long ull;

// ---------------- packed f32x2 helpers ----------------
__device__ __forceinline__ ull f32x2_add(ull a, ull b) {
    ull r; asm("add.rn.f32x2 %0, %1, %2;" : "=l"(r) : "l"(a), "l"(b)); return r;
}
__device__ __forceinline__ ull f32x2_fma(ull a, ull b, ull c) {
    ull r; asm("fma.rn.f32x2 %0, %1, %2, %3;" : "=l"(r) : "l"(a), "l"(b), "l"(c)); return r;
}
__device__ __forceinline__ ull pack2(float a, float b) {
    ull r; asm("mov.b64 %0, {%1, %2};" : "=l"(r) : "f"(a), "f"(b)); return r;
}
__device__ __forceinline__ float lo32(ull v) { return __uint_as_float((unsigned)v); }
__device__ __forceinline__ float hi32(ull v) { return __uint_as_float((unsigned)(v >> 32)); }
__device__ __forceinline__ float sqrt_ap(float x) {
    float r; asm("sqrt.approx.f32 %0, %1;" : "=f"(r) : "f"(x)); return r;
}
__device__ __forceinline__ float rsqrt_ap(float x) {
    float r; asm("rsqrt.approx.f32 %0, %1;" : "=f"(r) : "f"(x)); return r;
}

// ---------------- fused distance kernel ----------------
// Tile: 32 q x 32 m per CTA, 128 threads (tx=tid&15 -> m pairs, ty=tid>>4 -> q quads),
// 4q x 2m outputs per thread. ALL of D (64 f32x2 dpairs) staged up front in SMEM as
// [dpair][row] (rows padded to 34 ull = 272B, keeping 16B alignment for LDS.128),
// so the compute loop runs 64 dpairs with NO internal barriers. y staged NEGATED:
// diff = add.f32x2(x, -y). Row norms (for cos via polarization) computed in-kernel:
// 2 threads per staged row, 32 dpairs each.
__global__ __launch_bounds__(128, 6) void dist_main(
    const float* __restrict__ x, const float* __restrict__ y, float* __restrict__ out)
{
    __shared__ __align__(16) ull sx[64][34];   // [dpair][q_local], full D resident
    __shared__ __align__(16) ull sy[64][34];   // [dpair][m_local], holds -y
    __shared__ float s_part[128];
    __shared__ float s_xn2[32], s_xrn[32], s_yn2[32], s_yrn[32];

    const int tid = threadIdx.x;
    const int tx = tid & 15;         // m direction (2 cols each)
    const int ty = tid >> 4;         // q direction (4 rows each)
    const int q0 = blockIdx.y * 32;
    const int m0 = blockIdx.x * 32;

    ull accL[4][2];  // packed L1 partial sums
    ull accS[4][2];  // packed squared-diff partial sums
    #pragma unroll
    for (int i = 0; i < 4; i++)
        #pragma unroll
        for (int j = 0; j < 2; j++) { accL[i][j] = 0ull; accS[i][j] = 0ull; }

    const float4* x4 = reinterpret_cast<const float4*>(x);
    const float4* y4 = reinterpret_cast<const float4*>(y);

    // ---- stage ALL of D: 64 rows (32 x + 32 y) x 128 floats = 32 float4 each ----
    // 2048 float4 over 128 threads -> 16 iters; row = idx>>5 advances 4 per t, so
    // the x/y branch flips exactly at t=8 and stays warp-uniform.
    #pragma unroll
    for (int t = 0; t < 16; ++t) {
        int idx = tid + t * 128;      // 0..2047
        int row = idx >> 5;           // 0..63
        int c4  = idx & 31;           // float4 column (0..31 covers D=128)
        if (row < 32) {
            float4 v = x4[(size_t)(q0 + row) * (D_TOT / 4) + c4];
            sx[c4 * 2][row]     = pack2(v.x, v.y);
            sx[c4 * 2 + 1][row] = pack2(v.z, v.w);
        } else {
            int r = row - 32;
            float4 v = y4[(size_t)(m0 + r) * (D_TOT / 4) + c4];
            sy[c4 * 2][r]     = pack2(-v.x, -v.y);
            sy[c4 * 2 + 1][r] = pack2(-v.z, -v.w);
        }
    }
    __syncthreads();    // sync #1: staged tiles visible

    // ---- norm partials: 2 threads per staged row, 32 dpairs each ----
    {
        const int nrow  = tid & 63;   // staged row (0..31 x, 32..63 y)
        const int nhalf = tid >> 6;   // which 32 dpairs
        const ull* src = (nrow < 32) ? &sx[0][nrow] : &sy[0][nrow - 32];
        src += (size_t)(nhalf * 32) * 34;
        float na = 0.0f, nb = 0.0f;
        #pragma unroll 8
        for (int dp = 0; dp < 32; dp += 2) {
            ull v0 = src[(size_t)dp * 34];
            ull v1 = src[(size_t)(dp + 1) * 34];
            float a0 = lo32(v0), b0 = hi32(v0);
            float a1 = lo32(v1), b1 = hi32(v1);
            na = fmaf(a0, a0, fmaf(b0, b0, na));
            nb = fmaf(a1, a1, fmaf(b1, b1, nb));
        }
        s_part[tid] = na + nb;        // consumed after sync #2
    }

    // ---- compute: 64 dpairs straight through, 8 packed pairs/thread/dpair ----
    #pragma unroll 4
    for (int dp = 0; dp < 64; ++dp) {
        // xr: 2x LDS.128 (8 distinct addrs per warp -> broadcast-friendly)
        ulonglong2 xa = *reinterpret_cast<const ulonglong2*>(&sx[dp][ty * 4]);
        ulonglong2 xb = *reinterpret_cast<const ulonglong2*>(&sx[dp][ty * 4 + 2]);
        // yr: 1x LDS.128 (16 distinct 16B addrs in one 272B-strided row)
        ulonglong2 yv = *reinterpret_cast<const ulonglong2*>(&sy[dp][tx * 2]);
        ull xr[4] = { xa.x, xa.y, xb.x, xb.y };
        ull yr[2] = { yv.x, yv.y };
        #pragma unroll
        for (int i = 0; i < 4; i++) {
            #pragma unroll
            for (int j = 0; j < 2; j++) {
                ull d  = f32x2_add(xr[i], yr[j]);            // x - y (packed)
                ull ad = d & 0x7FFFFFFF7FFFFFFFull;          // packed |.| (alu pipe)
                accL[i][j] = f32x2_add(accL[i][j], ad);
                accS[i][j] = f32x2_fma(d, d, accS[i][j]);
            }
        }
    }
    __syncthreads();    // sync #2: s_part complete everywhere

    // ---- publish norms: combine the two half-row partials ----
    if (tid < 64) {
        float n2 = s_part[tid] + s_part[tid + 64];
        float rn = rsqrt_ap(n2);
        if (tid < 32) { s_xn2[tid] = n2; s_xrn[tid] = rn; }
        else          { s_yn2[tid - 32] = n2; s_yrn[tid - 32] = rn; }
    }
    __syncthreads();    // sync #3: norms visible

    // ---- epilogue: fold packed halves, cos via polarization identity ----
    float xn2[4], xrn[4], yn2[2], yrn[2];
    #pragma unroll
    for (int i = 0; i < 4; i++) { xn2[i] = s_xn2[ty * 4 + i]; xrn[i] = s_xrn[ty * 4 + i]; }
    #pragma unroll
    for (int j = 0; j < 2; j++) { yn2[j] = s_yn2[tx * 2 + j]; yrn[j] = s_yrn[tx * 2 + j]; }

    #pragma unroll
    for (int i = 0; i < 4; i++) {
        int q = q0 + ty * 4 + i;
        float r[6];
        #pragma unroll
        for (int j = 0; j < 2; j++) {
            float l1 = lo32(accL[i][j]) + hi32(accL[i][j]);
            float sq = lo32(accS[i][j]) + hi32(accS[i][j]);
            float p2 = sqrt_ap(sq);
            // x.y = (||x||^2 + ||y||^2 - ||x-y||^2) / 2 ; cos = x.y / (||x|| ||y||)
            float cs = (xn2[i] + yn2[j] - sq) * 0.5f * xrn[i] * yrn[j];
            r[3 * j + 0] = cs;
            r[3 * j + 1] = l1;
            r[3 * j + 2] = p2;
        }
        // 2 consecutive m -> 6 contiguous floats (8B aligned): 3x STG.64
        float2* o = reinterpret_cast<float2*>(out + ((size_t)q * M_TOT + (m0 + tx * 2)) * 3);
        o[0] = make_float2(r[0], r[1]);
        o[1] = make_float2(r[2], r[3]);
        o[2] = make_float2(r[4], r[5]);
    }
}

extern "C" void kernel_launch(void* const* d_in, const int* in_sizes, int n_in,
                              void* d_out, int out_size) {
    const float* x = (const float*)d_in[0];   // [4,512,128]
    const float* y = (const float*)d_in[1];   // [512,128]
    float* out = (float*)d_out;               // [4,512,512,3]

    dim3 grid(M_TOT / 32, Q_TOT / 32);        // (16, 64) = 1024 CTAs, 4096 warps
    dist_main<<<grid, 128>>>(x, y, out);
}

// round 17
// speedup vs baseline: 1.0913x; 1.0142x over previous
#include <cuda_runtime.h>
#include <cstdint>

// Fixed shapes: x [4,512,128] -> Q=2048 rows, y [512,128] -> M=512, D=128,
// out [Q, M, 3] f32 (cos, p1, p2).
#define Q_TOT 2048
#define M_TOT 512
#define D_TOT 128

typedef unsigned long long ull;

// ---------------- packed f32x2 helpers ----------------
__device__ __forceinline__ ull f32x2_add(ull a, ull b) {
    ull r; asm("add.rn.f32x2 %0, %1, %2;" : "=l"(r) : "l"(a), "l"(b)); return r;
}
__device__ __forceinline__ ull f32x2_fma(ull a, ull b, ull c) {
    ull r; asm("fma.rn.f32x2 %0, %1, %2, %3;" : "=l"(r) : "l"(a), "l"(b), "l"(c)); return r;
}
__device__ __forceinline__ ull pack2(float a, float b) {
    ull r; asm("mov.b64 %0, {%1, %2};" : "=l"(r) : "f"(a), "f"(b)); return r;
}
__device__ __forceinline__ float lo32(ull v) { return __uint_as_float((unsigned)v); }
__device__ __forceinline__ float hi32(ull v) { return __uint_as_float((unsigned)(v >> 32)); }
__device__ __forceinline__ float sqrt_ap(float x) {
    float r; asm("sqrt.approx.f32 %0, %1;" : "=f"(r) : "f"(x)); return r;
}
__device__ __forceinline__ float rsqrt_ap(float x) {
    float r; asm("rsqrt.approx.f32 %0, %1;" : "=f"(r) : "f"(x)); return r;
}

// ---------------- fused distance kernel ----------------
// Tile: 32 q x 32 m per CTA, 128 threads (tx=tid&15 -> m pairs, ty=tid>>4 -> q quads),
// 4q x 2m outputs per thread. ALL of D (64 f32x2 dpairs) staged up front in SMEM as
// [dpair][row] (rows padded to 34 ull = 272B, keeping 16B alignment for LDS.128),
// so the compute loop runs 64 dpairs with NO internal barriers. y staged NEGATED:
// diff = add.f32x2(x, -y). Row norms (for cos via polarization) computed in-kernel:
// 2 threads per staged row, 32 dpairs each.
__global__ __launch_bounds__(128, 6) void dist_main(
    const float* __restrict__ x, const float* __restrict__ y, float* __restrict__ out)
{
    __shared__ __align__(16) ull sx[64][34];   // [dpair][q_local], full D resident
    __shared__ __align__(16) ull sy[64][34];   // [dpair][m_local], holds -y
    __shared__ float s_part[128];
    __shared__ float s_xn2[32], s_xrn[32], s_yn2[32], s_yrn[32];

    const int tid = threadIdx.x;
    const int tx = tid & 15;         // m direction (2 cols each)
    const int ty = tid >> 4;         // q direction (4 rows each)
    const int q0 = blockIdx.y * 32;
    const int m0 = blockIdx.x * 32;

    ull accL[4][2];  // packed L1 partial sums
    ull accS[4][2];  // packed squared-diff partial sums
    #pragma unroll
    for (int i = 0; i < 4; i++)
        #pragma unroll
        for (int j = 0; j < 2; j++) { accL[i][j] = 0ull; accS[i][j] = 0ull; }

    const float4* x4 = reinterpret_cast<const float4*>(x);
    const float4* y4 = reinterpret_cast<const float4*>(y);

    // ---- stage ALL of D: 64 rows (32 x + 32 y) x 128 floats = 32 float4 each ----
    // 2048 float4 over 128 threads -> 16 iters; row = idx>>5 advances 4 per t, so
    // the x/y branch flips exactly at t=8 and stays warp-uniform.
    #pragma unroll
    for (int t = 0; t < 16; ++t) {
        int idx = tid + t * 128;      // 0..2047
        int row = idx >> 5;           // 0..63
        int c4  = idx & 31;           // float4 column (0..31 covers D=128)
        if (row < 32) {
            float4 v = x4[(size_t)(q0 + row) * (D_TOT / 4) + c4];
            sx[c4 * 2][row]     = pack2(v.x, v.y);
            sx[c4 * 2 + 1][row] = pack2(v.z, v.w);
        } else {
            int r = row - 32;
            float4 v = y4[(size_t)(m0 + r) * (D_TOT / 4) + c4];
            sy[c4 * 2][r]     = pack2(-v.x, -v.y);
            sy[c4 * 2 + 1][r] = pack2(-v.z, -v.w);
        }
    }
    __syncthreads();    // sync #1: staged tiles visible

    // ---- norm partials: 2 threads per staged row, 32 dpairs each ----
    {
        const int nrow  = tid & 63;   // staged row (0..31 x, 32..63 y)
        const int nhalf = tid >> 6;   // which 32 dpairs
        const ull* src = (nrow < 32) ? &sx[0][nrow] : &sy[0][nrow - 32];
        src += (size_t)(nhalf * 32) * 34;
        float na = 0.0f, nb = 0.0f;
        #pragma unroll 8
        for (int dp = 0; dp < 32; dp += 2) {
            ull v0 = src[(size_t)dp * 34];
            ull v1 = src[(size_t)(dp + 1) * 34];
            float a0 = lo32(v0), b0 = hi32(v0);
            float a1 = lo32(v1), b1 = hi32(v1);
            na = fmaf(a0, a0, fmaf(b0, b0, na));
            nb = fmaf(a1, a1, fmaf(b1, b1, nb));
        }
        s_part[tid] = na + nb;        // consumed after sync #2
    }

    // ---- compute: 64 dpairs straight through, 8 packed pairs/thread/dpair ----
    #pragma unroll 4
    for (int dp = 0; dp < 64; ++dp) {
        // xr: 2x LDS.128 (8 distinct addrs per warp -> broadcast-friendly)
        ulonglong2 xa = *reinterpret_cast<const ulonglong2*>(&sx[dp][ty * 4]);
        ulonglong2 xb = *reinterpret_cast<const ulonglong2*>(&sx[dp][ty * 4 + 2]);
        // yr: 1x LDS.128 (16 distinct 16B addrs in one 272B-strided row)
        ulonglong2 yv = *reinterpret_cast<const ulonglong2*>(&sy[dp][tx * 2]);
        ull xr[4] = { xa.x, xa.y, xb.x, xb.y };
        ull yr[2] = { yv.x, yv.y };
        #pragma unroll
        for (int i = 0; i < 4; i++) {
            #pragma unroll
            for (int j = 0; j < 2; j++) {
                ull d  = f32x2_add(xr[i], yr[j]);            // x - y (packed)
                ull ad = d & 0x7FFFFFFF7FFFFFFFull;          // packed |.| (alu pipe)
                accL[i][j] = f32x2_add(accL[i][j], ad);
                accS[i][j] = f32x2_fma(d, d, accS[i][j]);
            }
        }
    }
    __syncthreads();    // sync #2: s_part complete everywhere

    // ---- publish norms: combine the two half-row partials ----
    if (tid < 64) {
        float n2 = s_part[tid] + s_part[tid + 64];
        float rn = rsqrt_ap(n2);
        if (tid < 32) { s_xn2[tid] = n2; s_xrn[tid] = rn; }
        else          { s_yn2[tid - 32] = n2; s_yrn[tid - 32] = rn; }
    }
    __syncthreads();    // sync #3: norms visible

    // ---- epilogue: fold packed halves, cos via polarization identity ----
    float xn2[4], xrn[4], yn2[2], yrn[2];
    #pragma unroll
    for (int i = 0; i < 4; i++) { xn2[i] = s_xn2[ty * 4 + i]; xrn[i] = s_xrn[ty * 4 + i]; }
    #pragma unroll
    for (int j = 0; j < 2; j++) { yn2[j] = s_yn2[tx * 2 + j]; yrn[j] = s_yrn[tx * 2 + j]; }

    #pragma unroll
    for (int i = 0; i < 4; i++) {
        int q = q0 + ty * 4 + i;
        float r[6];
        #pragma unroll
        for (int j = 0; j < 2; j++) {
            float l1 = lo32(accL[i][j]) + hi32(accL[i][j]);
            float sq = lo32(accS[i][j]) + hi32(accS[i][j]);
            float p2 = sqrt_ap(sq);
            // x.y = (||x||^2 + ||y||^2 - ||x-y||^2) / 2 ; cos = x.y / (||x|| ||y||)
            float cs = (xn2[i] + yn2[j] - sq) * 0.5f * xrn[i] * yrn[j];
            r[3 * j + 0] = cs;
            r[3 * j + 1] = l1;
            r[3 * j + 2] = p2;
        }
        // 2 consecutive m -> 6 contiguous floats (8B aligned): 3x STG.64
        float2* o = reinterpret_cast<float2*>(out + ((size_t)q * M_TOT + (m0 + tx * 2)) * 3);
        o[0] = make_float2(r[0], r[1]);
        o[1] = make_float2(r[2], r[3]);
        o[2] = make_float2(r[4], r[5]);
    }
}

extern "C" void kernel_launch(void* const* d_in, const int* in_sizes, int n_in,
                              void* d_out, int out_size) {
    const float* x = (const float*)d_in[0];   // [4,512,128]
    const float* y = (const float*)d_in[1];   // [512,128]
    float* out = (float*)d_out;               // [4,512,512,3]

    dim3 grid(M_TOT / 32, Q_TOT / 32);        // (16, 64) = 1024 CTAs, 4096 warps
    dist_main<<<grid, 128>>>(x, y, out);
}